// round 1
// baseline (speedup 1.0000x reference)
#include <cuda_runtime.h>

#define BB   8
#define LL   384
#define HIDD 512
#define NHH  8
#define DHH  64
#define MM   768   // 2*MAX_SEQ_LEN rows of pe / R

// ---------------- scratch (device globals, no allocation) ----------------
__device__ float g_K[BB*LL*HIDD];        // key proj   [b, l, h*64+d]
__device__ float g_Q[BB*LL*HIDD];        // query proj
__device__ float g_V[BB*LL*HIDD];        // value proj
__device__ float g_R[MM*HIDD];           // pe @ Wr.T + br
__device__ float g_Qrel[BB*NHH*LL*MM];   // (q+v_bias) . R[m]   [bh, i, m]
__device__ float g_O[BB*LL*HIDD];        // attention output pre-final-proj

// ---------------- generic NT GEMM: out[n][o] = sum_k X[n][k]*W[o][k] + bias[o]
// K = O = 512 fixed. Grid: (O/64, N/64), 256 threads, 4x4 micro-tile.
__global__ __launch_bounds__(256) void gemm512_nt(
    const float* __restrict__ X, const float* __restrict__ W,
    const float* __restrict__ bias, float* __restrict__ out)
{
    __shared__ float As[16][68];
    __shared__ float Bs[16][68];
    const int n0 = blockIdx.y * 64, o0 = blockIdx.x * 64;
    const int t  = threadIdx.x;
    const int tx = t & 15, ty = t >> 4;
    const int lm = t >> 2, lk = (t & 3) * 4;

    float acc[4][4] = {};
    for (int k0 = 0; k0 < 512; k0 += 16) {
        float4 a = *(const float4*)(X + (size_t)(n0 + lm) * 512 + k0 + lk);
        float4 w = *(const float4*)(W + (size_t)(o0 + lm) * 512 + k0 + lk);
        As[lk+0][lm] = a.x; As[lk+1][lm] = a.y; As[lk+2][lm] = a.z; As[lk+3][lm] = a.w;
        Bs[lk+0][lm] = w.x; Bs[lk+1][lm] = w.y; Bs[lk+2][lm] = w.z; Bs[lk+3][lm] = w.w;
        __syncthreads();
        #pragma unroll
        for (int k = 0; k < 16; k++) {
            float4 a4 = *(const float4*)&As[k][ty * 4];
            float4 b4 = *(const float4*)&Bs[k][tx * 4];
            float ar[4] = {a4.x, a4.y, a4.z, a4.w};
            float br_[4] = {b4.x, b4.y, b4.z, b4.w};
            #pragma unroll
            for (int i = 0; i < 4; i++)
                #pragma unroll
                for (int j = 0; j < 4; j++)
                    acc[i][j] = fmaf(ar[i], br_[j], acc[i][j]);
        }
        __syncthreads();
    }
    float4 bv = *(const float4*)(bias + o0 + tx * 4);
    #pragma unroll
    for (int i = 0; i < 4; i++) {
        float4 o;
        o.x = acc[i][0] + bv.x; o.y = acc[i][1] + bv.y;
        o.z = acc[i][2] + bv.z; o.w = acc[i][3] + bv.w;
        *(float4*)(out + (size_t)(n0 + ty * 4 + i) * 512 + o0 + tx * 4) = o;
    }
}

// ---------------- Qrel[b,h,i,m] = sum_d (Q[b,i,h*64+d] + v_bias[h*64+d]) * R[m, h*64+d]
// Grid: (MM/64, LL/64, BB*NHH), 256 threads.
__global__ __launch_bounds__(256) void qrel_kernel(const float* __restrict__ vbias)
{
    __shared__ float As[16][68];
    __shared__ float Bs[16][68];
    const int b = blockIdx.z >> 3, h = blockIdx.z & 7;
    const int i0 = blockIdx.y * 64, m0 = blockIdx.x * 64;
    const float* Qb = g_Q + (size_t)b * LL * HIDD + h * 64;
    const float* Rb = g_R + h * 64;
    const int t = threadIdx.x;
    const int tx = t & 15, ty = t >> 4;
    const int lm = t >> 2, lk = (t & 3) * 4;

    float acc[4][4] = {};
    for (int k0 = 0; k0 < 64; k0 += 16) {
        float4 a  = *(const float4*)(Qb + (size_t)(i0 + lm) * 512 + k0 + lk);
        float4 vb = *(const float4*)(vbias + h * 64 + k0 + lk);
        a.x += vb.x; a.y += vb.y; a.z += vb.z; a.w += vb.w;
        float4 w  = *(const float4*)(Rb + (size_t)(m0 + lm) * 512 + k0 + lk);
        As[lk+0][lm] = a.x; As[lk+1][lm] = a.y; As[lk+2][lm] = a.z; As[lk+3][lm] = a.w;
        Bs[lk+0][lm] = w.x; Bs[lk+1][lm] = w.y; Bs[lk+2][lm] = w.z; Bs[lk+3][lm] = w.w;
        __syncthreads();
        #pragma unroll
        for (int k = 0; k < 16; k++) {
            float4 a4 = *(const float4*)&As[k][ty * 4];
            float4 b4 = *(const float4*)&Bs[k][tx * 4];
            float ar[4] = {a4.x, a4.y, a4.z, a4.w};
            float br_[4] = {b4.x, b4.y, b4.z, b4.w};
            #pragma unroll
            for (int i = 0; i < 4; i++)
                #pragma unroll
                for (int j = 0; j < 4; j++)
                    acc[i][j] = fmaf(ar[i], br_[j], acc[i][j]);
        }
        __syncthreads();
    }
    float* dst = g_Qrel + ((size_t)(b * NHH + h) * LL + i0) * MM + m0;
    #pragma unroll
    for (int i = 0; i < 4; i++) {
        float4 o;
        o.x = acc[i][0]; o.y = acc[i][1]; o.z = acc[i][2]; o.w = acc[i][3];
        *(float4*)(dst + (size_t)(ty * 4 + i) * MM + tx * 4) = o;
    }
}

// ---------------- attention: per (i-tile of 64, b, h)
// S[i][j] = ((q_i+u).k_j + Qrel[i][j-i+384]) / 8, mask j>=seq_len, softmax, O = P@V
#define SROW 390
#define SMEM_ATTN ((2 * 64 * 68 + 64 * SROW) * 4)

__global__ __launch_bounds__(256) void attn_kernel(
    const float* __restrict__ ubias, const int* __restrict__ seq_len)
{
    extern __shared__ float sm[];
    float* sQuT = sm;                 // [d][i], stride 68
    float* sKT  = sm + 64 * 68;       // [d][j], stride 68 (reused as sV [j][d])
    float* sS   = sm + 2 * 64 * 68;   // [i][j], stride SROW

    const int i0 = blockIdx.x * 64;
    const int b  = blockIdx.y >> 3, h = blockIdx.y & 7;
    const int slen = seq_len[b];
    const int t = threadIdx.x;
    const int tx = t & 15, ty = t >> 4;
    const int lj = t >> 2, lk4 = (t & 3) * 4;

    // load Q tile + u_bias, transposed [d][i]
    #pragma unroll
    for (int r = 0; r < 4; r++) {
        int d0 = r * 16 + lk4;
        float4 q  = *(const float4*)(g_Q + ((size_t)(b * LL + i0 + lj)) * HIDD + h * 64 + d0);
        float4 u4 = *(const float4*)(ubias + h * 64 + d0);
        sQuT[(d0+0) * 68 + lj] = q.x + u4.x;
        sQuT[(d0+1) * 68 + lj] = q.y + u4.y;
        sQuT[(d0+2) * 68 + lj] = q.z + u4.z;
        sQuT[(d0+3) * 68 + lj] = q.w + u4.w;
    }
    __syncthreads();

    const float* qr = g_Qrel + (size_t)(b * NHH + h) * LL * MM;

    // ---- score phase ----
    for (int jt = 0; jt < 6; jt++) {
        const int j0 = jt * 64;
        #pragma unroll
        for (int r = 0; r < 4; r++) {
            int d0 = r * 16 + lk4;
            float4 kv = *(const float4*)(g_K + ((size_t)(b * LL + j0 + lj)) * HIDD + h * 64 + d0);
            sKT[(d0+0) * 68 + lj] = kv.x;
            sKT[(d0+1) * 68 + lj] = kv.y;
            sKT[(d0+2) * 68 + lj] = kv.z;
            sKT[(d0+3) * 68 + lj] = kv.w;
        }
        __syncthreads();
        float acc[4][4] = {};
        #pragma unroll 16
        for (int d = 0; d < 64; d++) {
            float4 a4 = *(const float4*)&sQuT[d * 68 + ty * 4];
            float4 b4 = *(const float4*)&sKT[d * 68 + tx * 4];
            float ar[4] = {a4.x, a4.y, a4.z, a4.w};
            float br_[4] = {b4.x, b4.y, b4.z, b4.w};
            #pragma unroll
            for (int i = 0; i < 4; i++)
                #pragma unroll
                for (int j = 0; j < 4; j++)
                    acc[i][j] = fmaf(ar[i], br_[j], acc[i][j]);
        }
        #pragma unroll
        for (int ii = 0; ii < 4; ii++) {
            const int i = i0 + ty * 4 + ii;
            #pragma unroll
            for (int jj = 0; jj < 4; jj++) {
                const int j = j0 + tx * 4 + jj;
                float s = (acc[ii][jj] + qr[(size_t)i * MM + (j - i + 384)]) * 0.125f;
                if (j >= slen) s = -1e15f;
                sS[(ty * 4 + ii) * SROW + j] = s;
            }
        }
        __syncthreads();
    }

    // ---- softmax over j (each warp owns 8 rows) ----
    {
        const int w = t >> 5, lane = t & 31;
        for (int rr = 0; rr < 8; rr++) {
            float* Srow = sS + (w * 8 + rr) * SROW;
            float mx = -3.4e38f;
            for (int j = lane; j < 384; j += 32) mx = fmaxf(mx, Srow[j]);
            #pragma unroll
            for (int off = 16; off; off >>= 1)
                mx = fmaxf(mx, __shfl_xor_sync(0xffffffffu, mx, off));
            float sum = 0.f;
            for (int j = lane; j < 384; j += 32) {
                float e = __expf(Srow[j] - mx);
                Srow[j] = e; sum += e;
            }
            #pragma unroll
            for (int off = 16; off; off >>= 1)
                sum += __shfl_xor_sync(0xffffffffu, sum, off);
            float inv = 1.f / sum;
            for (int j = lane; j < 384; j += 32) Srow[j] *= inv;
        }
    }

    // ---- P @ V phase ----
    float* sV = sKT;  // reuse, now [j][d] stride 68
    float accO[4][4] = {};
    for (int jt = 0; jt < 6; jt++) {
        const int j0 = jt * 64;
        __syncthreads();   // softmax done (jt=0) / previous compute done
        #pragma unroll
        for (int r = 0; r < 4; r++) {
            int d0 = r * 16 + lk4;
            float4 vv = *(const float4*)(g_V + ((size_t)(b * LL + j0 + lj)) * HIDD + h * 64 + d0);
            *(float4*)&sV[lj * 68 + d0] = vv;
        }
        __syncthreads();
        #pragma unroll 8
        for (int j = 0; j < 64; j++) {
            float4 v4 = *(const float4*)&sV[j * 68 + tx * 4];
            float p0 = sS[(ty * 4 + 0) * SROW + j0 + j];
            float p1 = sS[(ty * 4 + 1) * SROW + j0 + j];
            float p2 = sS[(ty * 4 + 2) * SROW + j0 + j];
            float p3 = sS[(ty * 4 + 3) * SROW + j0 + j];
            accO[0][0] = fmaf(p0, v4.x, accO[0][0]); accO[0][1] = fmaf(p0, v4.y, accO[0][1]);
            accO[0][2] = fmaf(p0, v4.z, accO[0][2]); accO[0][3] = fmaf(p0, v4.w, accO[0][3]);
            accO[1][0] = fmaf(p1, v4.x, accO[1][0]); accO[1][1] = fmaf(p1, v4.y, accO[1][1]);
            accO[1][2] = fmaf(p1, v4.z, accO[1][2]); accO[1][3] = fmaf(p1, v4.w, accO[1][3]);
            accO[2][0] = fmaf(p2, v4.x, accO[2][0]); accO[2][1] = fmaf(p2, v4.y, accO[2][1]);
            accO[2][2] = fmaf(p2, v4.z, accO[2][2]); accO[2][3] = fmaf(p2, v4.w, accO[2][3]);
            accO[3][0] = fmaf(p3, v4.x, accO[3][0]); accO[3][1] = fmaf(p3, v4.y, accO[3][1]);
            accO[3][2] = fmaf(p3, v4.z, accO[3][2]); accO[3][3] = fmaf(p3, v4.w, accO[3][3]);
        }
    }
    #pragma unroll
    for (int ii = 0; ii < 4; ii++) {
        float4 o;
        o.x = accO[ii][0]; o.y = accO[ii][1]; o.z = accO[ii][2]; o.w = accO[ii][3];
        *(float4*)(g_O + ((size_t)(b * LL + i0 + ty * 4 + ii)) * HIDD + h * 64 + tx * 4) = o;
    }
}

// ---------------- launch ----------------
extern "C" void kernel_launch(void* const* d_in, const int* in_sizes, int n_in,
                              void* d_out, int out_size)
{
    const float* key    = (const float*)d_in[0];
    const float* query  = (const float*)d_in[1];
    const float* value  = (const float*)d_in[2];
    const int*   slen   = (const int*)  d_in[3];
    const float* pe     = (const float*)d_in[4];
    const float* Wk     = (const float*)d_in[5];
    const float* bk     = (const float*)d_in[6];
    const float* Wq     = (const float*)d_in[7];
    const float* bq     = (const float*)d_in[8];
    const float* Wv     = (const float*)d_in[9];
    const float* bv     = (const float*)d_in[10];
    const float* Wr     = (const float*)d_in[11];
    const float* br     = (const float*)d_in[12];
    const float* u_bias = (const float*)d_in[13];
    const float* v_bias = (const float*)d_in[14];
    const float* Wf     = (const float*)d_in[15];
    const float* bf     = (const float*)d_in[16];

    float *pK, *pQ, *pV, *pR, *pO;
    cudaGetSymbolAddress((void**)&pK, g_K);
    cudaGetSymbolAddress((void**)&pQ, g_Q);
    cudaGetSymbolAddress((void**)&pV, g_V);
    cudaGetSymbolAddress((void**)&pR, g_R);
    cudaGetSymbolAddress((void**)&pO, g_O);

    cudaFuncSetAttribute(attn_kernel, cudaFuncAttributeMaxDynamicSharedMemorySize, SMEM_ATTN);

    dim3 blk(256);
    gemm512_nt<<<dim3(8, 48), blk>>>(key,   Wk, bk, pK);
    gemm512_nt<<<dim3(8, 48), blk>>>(query, Wq, bq, pQ);
    gemm512_nt<<<dim3(8, 48), blk>>>(value, Wv, bv, pV);
    gemm512_nt<<<dim3(8, 12), blk>>>(pe,    Wr, br, pR);
    qrel_kernel<<<dim3(12, 6, 64), blk>>>(v_bias);
    attn_kernel<<<dim3(6, 64), blk, SMEM_ATTN>>>(u_bias, slen);
    gemm512_nt<<<dim3(8, 48), blk>>>(pO, Wf, bf, (float*)d_out);
}

// round 3
// speedup vs baseline: 1.3710x; 1.3710x over previous
#include <cuda_runtime.h>
#include <mma.h>
#include <cstdint>

using namespace nvcuda;

#define BB   8
#define LL   384
#define HIDD 512
#define NHH  8
#define MM   768   // 2*MAX_SEQ_LEN rows of pe / R

// ---------------- scratch (device globals, no allocation) ----------------
__device__ float g_K[BB*LL*HIDD];
__device__ float g_Q[BB*LL*HIDD];
__device__ float g_V[BB*LL*HIDD];
__device__ float g_R[MM*HIDD];
__device__ float g_Qrel[(size_t)BB*NHH*LL*MM];
__device__ float g_O[BB*LL*HIDD];

// =====================================================================
// wmma tf32 GEMM (NT): out[n][o] = sum_k X[n][k] * W[o][k] + bias[o]
// Block tile 128x128, K=512. 8 warps in 2(M)x4(N); warp tile 64x32.
// Merged: z selects one of up to 4 (X, W, bias, out) sets.
// =====================================================================
#define GPAD 20

__global__ __launch_bounds__(256) void tgemm512(
    const float* __restrict__ X0, const float* __restrict__ X1,
    const float* __restrict__ X2, const float* __restrict__ X3,
    const float* __restrict__ W0, const float* __restrict__ W1,
    const float* __restrict__ W2, const float* __restrict__ W3,
    const float* __restrict__ B0, const float* __restrict__ B1,
    const float* __restrict__ B2, const float* __restrict__ B3,
    float* __restrict__ O0, float* __restrict__ O1,
    float* __restrict__ O2, float* __restrict__ O3)
{
    __shared__ float sA[128 * GPAD];
    __shared__ float sB[128 * GPAD];

    const int z = blockIdx.z;
    if (z == 3 && blockIdx.y >= 6) return;   // pe/R source has only 768 rows
    const float* X  = z == 0 ? X0 : z == 1 ? X1 : z == 2 ? X2 : X3;
    const float* W  = z == 0 ? W0 : z == 1 ? W1 : z == 2 ? W2 : W3;
    const float* Bi = z == 0 ? B0 : z == 1 ? B1 : z == 2 ? B2 : B3;
    float*      Out = z == 0 ? O0 : z == 1 ? O1 : z == 2 ? O2 : O3;

    const int n0 = blockIdx.y * 128;
    const int o0 = blockIdx.x * 128;
    const int tid = threadIdx.x;
    const int wid = tid >> 5;
    const int lane = tid & 31;
    const int warp_m = wid & 1;        // 0..1  (64 rows each)
    const int warp_n = wid >> 1;       // 0..3  (32 cols each)

    wmma::fragment<wmma::accumulator, 16, 16, 8, float> acc[4][2];
    #pragma unroll
    for (int i = 0; i < 4; i++)
        #pragma unroll
        for (int j = 0; j < 2; j++)
            wmma::fill_fragment(acc[i][j], 0.0f);

    for (int kc = 0; kc < 512; kc += 16) {
        // load A,B chunk (128 x 16) into smem, tf32-converted
        #pragma unroll
        for (int i = 0; i < 2; i++) {
            int v = tid * 2 + i;            // 512 float4s
            int row = v >> 2, col = (v & 3) * 4;
            float4 a = *(const float4*)(X + (size_t)(n0 + row) * 512 + kc + col);
            float4 w = *(const float4*)(W + (size_t)(o0 + row) * 512 + kc + col);
            float* pa = sA + row * GPAD + col;
            float* pb = sB + row * GPAD + col;
            pa[0] = wmma::__float_to_tf32(a.x); pa[1] = wmma::__float_to_tf32(a.y);
            pa[2] = wmma::__float_to_tf32(a.z); pa[3] = wmma::__float_to_tf32(a.w);
            pb[0] = wmma::__float_to_tf32(w.x); pb[1] = wmma::__float_to_tf32(w.y);
            pb[2] = wmma::__float_to_tf32(w.z); pb[3] = wmma::__float_to_tf32(w.w);
        }
        __syncthreads();
        #pragma unroll
        for (int ks = 0; ks < 2; ks++) {
            wmma::fragment<wmma::matrix_a, 16, 16, 8, wmma::precision::tf32, wmma::row_major> af[4];
            wmma::fragment<wmma::matrix_b, 16, 16, 8, wmma::precision::tf32, wmma::col_major> bf[2];
            #pragma unroll
            for (int f = 0; f < 4; f++)
                wmma::load_matrix_sync(af[f], sA + (warp_m * 64 + f * 16) * GPAD + ks * 8, GPAD);
            #pragma unroll
            for (int g = 0; g < 2; g++)
                wmma::load_matrix_sync(bf[g], sB + (warp_n * 32 + g * 16) * GPAD + ks * 8, GPAD);
            #pragma unroll
            for (int f = 0; f < 4; f++)
                #pragma unroll
                for (int g = 0; g < 2; g++)
                    wmma::mma_sync(acc[f][g], af[f], bf[g], acc[f][g]);
        }
        __syncthreads();
    }

    // epilogue: stage each 16x16 frag through smem, add bias, vector store
    float* stage = sA + wid * (16 * GPAD);
    #pragma unroll
    for (int f = 0; f < 4; f++) {
        #pragma unroll
        for (int g = 0; g < 2; g++) {
            wmma::store_matrix_sync(stage, acc[f][g], GPAD, wmma::mem_row_major);
            __syncwarp();
            #pragma unroll
            for (int i = 0; i < 2; i++) {
                int v = lane * 2 + i;              // 64 float4s in 16x16
                int r = v >> 2, c = (v & 3) * 4;
                int orow = n0 + warp_m * 64 + f * 16 + r;
                int ocol = o0 + warp_n * 32 + g * 16 + c;
                float4 s = *(const float4*)(stage + r * GPAD + c);
                float4 bv = *(const float4*)(Bi + ocol);
                s.x += bv.x; s.y += bv.y; s.z += bv.z; s.w += bv.w;
                *(float4*)(Out + (size_t)orow * 512 + ocol) = s;
            }
            __syncwarp();
        }
    }
}

// =====================================================================
// Qrel[b,h,i,m] = sum_d (Q[b,i,h*64+d] + v_bias[h*64+d]) * R[m, h*64+d]
// wmma tf32, 64x64 tiles, K=64. 8 warps in 2(M)x4(N); warp tile 32x16.
// =====================================================================
__global__ __launch_bounds__(256) void qrel_kernel(const float* __restrict__ vbias)
{
    __shared__ float sA[64 * GPAD];
    __shared__ float sB[64 * GPAD];

    const int b = blockIdx.z >> 3, h = blockIdx.z & 7;
    const int i0 = blockIdx.y * 64, m0 = blockIdx.x * 64;
    if (m0 + 63 < 321 - i0 || m0 > 767 - i0) return;   // band skip
    const float* Qb = g_Q + (size_t)b * LL * HIDD + h * 64;
    const float* Rb = g_R + h * 64;

    const int tid = threadIdx.x;
    const int wid = tid >> 5;
    const int warp_m = wid & 1;       // 0..1 (32 rows)
    const int warp_n = wid >> 1;      // 0..3 (16 cols)

    wmma::fragment<wmma::accumulator, 16, 16, 8, float> acc[2];
    wmma::fill_fragment(acc[0], 0.0f);
    wmma::fill_fragment(acc[1], 0.0f);

    for (int kc = 0; kc < 64; kc += 16) {
        {
            int v = tid;                   // 256 float4s = 64x16
            int row = v >> 2, col = (v & 3) * 4;
            float4 a  = *(const float4*)(Qb + (size_t)(i0 + row) * 512 + kc + col);
            float4 vb = *(const float4*)(vbias + h * 64 + kc + col);
            float4 w  = *(const float4*)(Rb + (size_t)(m0 + row) * 512 + kc + col);
            float* pa = sA + row * GPAD + col;
            float* pb = sB + row * GPAD + col;
            pa[0] = wmma::__float_to_tf32(a.x + vb.x);
            pa[1] = wmma::__float_to_tf32(a.y + vb.y);
            pa[2] = wmma::__float_to_tf32(a.z + vb.z);
            pa[3] = wmma::__float_to_tf32(a.w + vb.w);
            pb[0] = wmma::__float_to_tf32(w.x); pb[1] = wmma::__float_to_tf32(w.y);
            pb[2] = wmma::__float_to_tf32(w.z); pb[3] = wmma::__float_to_tf32(w.w);
        }
        __syncthreads();
        #pragma unroll
        for (int ks = 0; ks < 2; ks++) {
            wmma::fragment<wmma::matrix_a, 16, 16, 8, wmma::precision::tf32, wmma::row_major> af[2];
            wmma::fragment<wmma::matrix_b, 16, 16, 8, wmma::precision::tf32, wmma::col_major> bf;
            wmma::load_matrix_sync(af[0], sA + (warp_m * 32 +  0) * GPAD + ks * 8, GPAD);
            wmma::load_matrix_sync(af[1], sA + (warp_m * 32 + 16) * GPAD + ks * 8, GPAD);
            wmma::load_matrix_sync(bf,    sB + (warp_n * 16) * GPAD + ks * 8, GPAD);
            wmma::mma_sync(acc[0], af[0], bf, acc[0]);
            wmma::mma_sync(acc[1], af[1], bf, acc[1]);
        }
        __syncthreads();
    }

    float* dst = g_Qrel + ((size_t)(b * NHH + h) * LL + i0) * MM + m0;
    #pragma unroll
    for (int f = 0; f < 2; f++)
        wmma::store_matrix_sync(
            dst + (size_t)(warp_m * 32 + f * 16) * MM + warp_n * 16,
            acc[f], MM, wmma::mem_row_major);
}

// ---------------- attention (unchanged, known-correct FFMA version) ----------------
#define SROW 390
#define SMEM_ATTN ((2 * 64 * 68 + 64 * SROW) * 4)

__global__ __launch_bounds__(256) void attn_kernel(
    const float* __restrict__ ubias, const int* __restrict__ seq_len)
{
    extern __shared__ float sm[];
    float* sQuT = sm;
    float* sKT  = sm + 64 * 68;
    float* sS   = sm + 2 * 64 * 68;

    const int i0 = blockIdx.x * 64;
    const int b  = blockIdx.y >> 3, h = blockIdx.y & 7;
    const int slen = seq_len[b];
    const int t = threadIdx.x;
    const int tx = t & 15, ty = t >> 4;
    const int lj = t >> 2, lk4 = (t & 3) * 4;

    #pragma unroll
    for (int r = 0; r < 4; r++) {
        int d0 = r * 16 + lk4;
        float4 q  = *(const float4*)(g_Q + ((size_t)(b * LL + i0 + lj)) * HIDD + h * 64 + d0);
        float4 u4 = *(const float4*)(ubias + h * 64 + d0);
        sQuT[(d0+0) * 68 + lj] = q.x + u4.x;
        sQuT[(d0+1) * 68 + lj] = q.y + u4.y;
        sQuT[(d0+2) * 68 + lj] = q.z + u4.z;
        sQuT[(d0+3) * 68 + lj] = q.w + u4.w;
    }
    __syncthreads();

    const float* qr = g_Qrel + (size_t)(b * NHH + h) * LL * MM;

    for (int jt = 0; jt < 6; jt++) {
        const int j0 = jt * 64;
        #pragma unroll
        for (int r = 0; r < 4; r++) {
            int d0 = r * 16 + lk4;
            float4 kv = *(const float4*)(g_K + ((size_t)(b * LL + j0 + lj)) * HIDD + h * 64 + d0);
            sKT[(d0+0) * 68 + lj] = kv.x;
            sKT[(d0+1) * 68 + lj] = kv.y;
            sKT[(d0+2) * 68 + lj] = kv.z;
            sKT[(d0+3) * 68 + lj] = kv.w;
        }
        __syncthreads();
        float acc[4][4] = {};
        #pragma unroll 16
        for (int d = 0; d < 64; d++) {
            float4 a4 = *(const float4*)&sQuT[d * 68 + ty * 4];
            float4 b4 = *(const float4*)&sKT[d * 68 + tx * 4];
            float ar[4] = {a4.x, a4.y, a4.z, a4.w};
            float br_[4] = {b4.x, b4.y, b4.z, b4.w};
            #pragma unroll
            for (int i = 0; i < 4; i++)
                #pragma unroll
                for (int j = 0; j < 4; j++)
                    acc[i][j] = fmaf(ar[i], br_[j], acc[i][j]);
        }
        #pragma unroll
        for (int ii = 0; ii < 4; ii++) {
            const int i = i0 + ty * 4 + ii;
            #pragma unroll
            for (int jj = 0; jj < 4; jj++) {
                const int j = j0 + tx * 4 + jj;
                float s = (acc[ii][jj] + qr[(size_t)i * MM + (j - i + 384)]) * 0.125f;
                if (j >= slen) s = -1e15f;
                sS[(ty * 4 + ii) * SROW + j] = s;
            }
        }
        __syncthreads();
    }

    {
        const int w = t >> 5, lane = t & 31;
        for (int rr = 0; rr < 8; rr++) {
            float* Srow = sS + (w * 8 + rr) * SROW;
            float mx = -3.4e38f;
            for (int j = lane; j < 384; j += 32) mx = fmaxf(mx, Srow[j]);
            #pragma unroll
            for (int off = 16; off; off >>= 1)
                mx = fmaxf(mx, __shfl_xor_sync(0xffffffffu, mx, off));
            float sum = 0.f;
            for (int j = lane; j < 384; j += 32) {
                float e = __expf(Srow[j] - mx);
                Srow[j] = e; sum += e;
            }
            #pragma unroll
            for (int off = 16; off; off >>= 1)
                sum += __shfl_xor_sync(0xffffffffu, sum, off);
            float inv = 1.f / sum;
            for (int j = lane; j < 384; j += 32) Srow[j] *= inv;
        }
    }

    float* sV = sKT;
    float accO[4][4] = {};
    for (int jt = 0; jt < 6; jt++) {
        const int j0 = jt * 64;
        __syncthreads();
        #pragma unroll
        for (int r = 0; r < 4; r++) {
            int d0 = r * 16 + lk4;
            float4 vv = *(const float4*)(g_V + ((size_t)(b * LL + j0 + lj)) * HIDD + h * 64 + d0);
            *(float4*)&sV[lj * 68 + d0] = vv;
        }
        __syncthreads();
        #pragma unroll 8
        for (int j = 0; j < 64; j++) {
            float4 v4 = *(const float4*)&sV[j * 68 + tx * 4];
            float p0 = sS[(ty * 4 + 0) * SROW + j0 + j];
            float p1 = sS[(ty * 4 + 1) * SROW + j0 + j];
            float p2 = sS[(ty * 4 + 2) * SROW + j0 + j];
            float p3 = sS[(ty * 4 + 3) * SROW + j0 + j];
            accO[0][0] = fmaf(p0, v4.x, accO[0][0]); accO[0][1] = fmaf(p0, v4.y, accO[0][1]);
            accO[0][2] = fmaf(p0, v4.z, accO[0][2]); accO[0][3] = fmaf(p0, v4.w, accO[0][3]);
            accO[1][0] = fmaf(p1, v4.x, accO[1][0]); accO[1][1] = fmaf(p1, v4.y, accO[1][1]);
            accO[1][2] = fmaf(p1, v4.z, accO[1][2]); accO[1][3] = fmaf(p1, v4.w, accO[1][3]);
            accO[2][0] = fmaf(p2, v4.x, accO[2][0]); accO[2][1] = fmaf(p2, v4.y, accO[2][1]);
            accO[2][2] = fmaf(p2, v4.z, accO[2][2]); accO[2][3] = fmaf(p2, v4.w, accO[2][3]);
            accO[3][0] = fmaf(p3, v4.x, accO[3][0]); accO[3][1] = fmaf(p3, v4.y, accO[3][1]);
            accO[3][2] = fmaf(p3, v4.z, accO[3][2]); accO[3][3] = fmaf(p3, v4.w, accO[3][3]);
        }
    }
    #pragma unroll
    for (int ii = 0; ii < 4; ii++) {
        float4 o;
        o.x = accO[ii][0]; o.y = accO[ii][1]; o.z = accO[ii][2]; o.w = accO[ii][3];
        *(float4*)(g_O + ((size_t)(b * LL + i0 + ty * 4 + ii)) * HIDD + h * 64 + tx * 4) = o;
    }
}

// ---------------- launch ----------------
extern "C" void kernel_launch(void* const* d_in, const int* in_sizes, int n_in,
                              void* d_out, int out_size)
{
    const float* key    = (const float*)d_in[0];
    const float* query  = (const float*)d_in[1];
    const float* value  = (const float*)d_in[2];
    const int*   slen   = (const int*)  d_in[3];
    const float* pe     = (const float*)d_in[4];
    const float* Wk     = (const float*)d_in[5];
    const float* bk     = (const float*)d_in[6];
    const float* Wq     = (const float*)d_in[7];
    const float* bq     = (const float*)d_in[8];
    const float* Wv     = (const float*)d_in[9];
    const float* bv     = (const float*)d_in[10];
    const float* Wr     = (const float*)d_in[11];
    const float* br_    = (const float*)d_in[12];
    const float* u_bias = (const float*)d_in[13];
    const float* v_bias = (const float*)d_in[14];
    const float* Wf     = (const float*)d_in[15];
    const float* bf     = (const float*)d_in[16];

    float *pK, *pQ, *pV, *pR, *pO;
    cudaGetSymbolAddress((void**)&pK, g_K);
    cudaGetSymbolAddress((void**)&pQ, g_Q);
    cudaGetSymbolAddress((void**)&pV, g_V);
    cudaGetSymbolAddress((void**)&pR, g_R);
    cudaGetSymbolAddress((void**)&pO, g_O);

    cudaFuncSetAttribute(attn_kernel, cudaFuncAttributeMaxDynamicSharedMemorySize, SMEM_ATTN);

    dim3 blk(256);
    // merged K/Q/V/R projections on wmma tf32
    tgemm512<<<dim3(4, 24, 4), blk>>>(
        key, query, value, pe,
        Wk, Wq, Wv, Wr,
        bk, bq, bv, br_,
        pK, pQ, pV, pR);
    qrel_kernel<<<dim3(12, 6, 64), blk>>>(v_bias);
    attn_kernel<<<dim3(6, 64), blk, SMEM_ATTN>>>(u_bias, slen);
    // final projection
    tgemm512<<<dim3(4, 24, 1), blk>>>(
        pO, nullptr, nullptr, nullptr,
        Wf, nullptr, nullptr, nullptr,
        bf, nullptr, nullptr, nullptr,
        (float*)d_out, nullptr, nullptr, nullptr);
}

// round 13
// speedup vs baseline: 1.7112x; 1.2481x over previous
#include <cuda_runtime.h>
#include <mma.h>
#include <cstdint>

using namespace nvcuda;

#define BB   8
#define LL   384
#define HIDD 512
#define NHH  8
#define MM   768   // 2*MAX_SEQ_LEN rows of pe / R

// ---------------- scratch (device globals, no allocation) ----------------
__device__ float g_K[BB*LL*HIDD];
__device__ float g_Q[BB*LL*HIDD];
__device__ float g_V[BB*LL*HIDD];
__device__ float g_R[MM*HIDD];
__device__ float g_Qrel[(size_t)BB*NHH*LL*MM];
__device__ float g_O[BB*LL*HIDD];

// =====================================================================
// wmma tf32 GEMM (NT), double-buffered: out[n][o] = X[n][:]·W[o][:] + b[o]
// Block tile 128x128, K=512 in 32 chunks of 16. 8 warps 2(M)x4(N).
// =====================================================================
#define GPAD 20

__global__ __launch_bounds__(256) void tgemm512(
    const float* __restrict__ X0, const float* __restrict__ X1,
    const float* __restrict__ X2, const float* __restrict__ X3,
    const float* __restrict__ W0, const float* __restrict__ W1,
    const float* __restrict__ W2, const float* __restrict__ W3,
    const float* __restrict__ B0, const float* __restrict__ B1,
    const float* __restrict__ B2, const float* __restrict__ B3,
    float* __restrict__ O0, float* __restrict__ O1,
    float* __restrict__ O2, float* __restrict__ O3)
{
    __shared__ float sA[2][128 * GPAD];
    __shared__ float sB[2][128 * GPAD];

    const int z = blockIdx.z;
    if (z == 3 && blockIdx.y >= 6) return;   // pe/R source has only 768 rows
    const float* X  = z == 0 ? X0 : z == 1 ? X1 : z == 2 ? X2 : X3;
    const float* W  = z == 0 ? W0 : z == 1 ? W1 : z == 2 ? W2 : W3;
    const float* Bi = z == 0 ? B0 : z == 1 ? B1 : z == 2 ? B2 : B3;
    float*      Out = z == 0 ? O0 : z == 1 ? O1 : z == 2 ? O2 : O3;

    const int n0 = blockIdx.y * 128;
    const int o0 = blockIdx.x * 128;
    const int tid = threadIdx.x;
    const int wid = tid >> 5;
    const int lane = tid & 31;
    const int warp_m = wid & 1;
    const int warp_n = wid >> 1;

    // per-thread load coords (2 float4 per matrix per 128x16 chunk)
    const int r0_ = (tid * 2) >> 2,       c0_ = ((tid * 2) & 3) * 4;
    const int r1_ = (tid * 2 + 1) >> 2,   c1_ = ((tid * 2 + 1) & 3) * 4;

    wmma::fragment<wmma::accumulator, 16, 16, 8, float> acc[4][2];
    #pragma unroll
    for (int i = 0; i < 4; i++)
        #pragma unroll
        for (int j = 0; j < 2; j++)
            wmma::fill_fragment(acc[i][j], 0.0f);

    float4 ra0, ra1, rb0, rb1;
    // preload chunk 0
    ra0 = *(const float4*)(X + (size_t)(n0 + r0_) * 512 + c0_);
    ra1 = *(const float4*)(X + (size_t)(n0 + r1_) * 512 + c1_);
    rb0 = *(const float4*)(W + (size_t)(o0 + r0_) * 512 + c0_);
    rb1 = *(const float4*)(W + (size_t)(o0 + r1_) * 512 + c1_);
    {
        float* pa0 = &sA[0][r0_ * GPAD + c0_]; float* pa1 = &sA[0][r1_ * GPAD + c1_];
        float* pb0 = &sB[0][r0_ * GPAD + c0_]; float* pb1 = &sB[0][r1_ * GPAD + c1_];
        pa0[0]=wmma::__float_to_tf32(ra0.x); pa0[1]=wmma::__float_to_tf32(ra0.y);
        pa0[2]=wmma::__float_to_tf32(ra0.z); pa0[3]=wmma::__float_to_tf32(ra0.w);
        pa1[0]=wmma::__float_to_tf32(ra1.x); pa1[1]=wmma::__float_to_tf32(ra1.y);
        pa1[2]=wmma::__float_to_tf32(ra1.z); pa1[3]=wmma::__float_to_tf32(ra1.w);
        pb0[0]=wmma::__float_to_tf32(rb0.x); pb0[1]=wmma::__float_to_tf32(rb0.y);
        pb0[2]=wmma::__float_to_tf32(rb0.z); pb0[3]=wmma::__float_to_tf32(rb0.w);
        pb1[0]=wmma::__float_to_tf32(rb1.x); pb1[1]=wmma::__float_to_tf32(rb1.y);
        pb1[2]=wmma::__float_to_tf32(rb1.z); pb1[3]=wmma::__float_to_tf32(rb1.w);
    }
    __syncthreads();

    for (int k = 0; k < 32; k++) {
        const int c = k & 1;
        if (k < 31) {
            const int kc = (k + 1) * 16;
            ra0 = *(const float4*)(X + (size_t)(n0 + r0_) * 512 + kc + c0_);
            ra1 = *(const float4*)(X + (size_t)(n0 + r1_) * 512 + kc + c1_);
            rb0 = *(const float4*)(W + (size_t)(o0 + r0_) * 512 + kc + c0_);
            rb1 = *(const float4*)(W + (size_t)(o0 + r1_) * 512 + kc + c1_);
        }
        #pragma unroll
        for (int ks = 0; ks < 2; ks++) {
            wmma::fragment<wmma::matrix_a, 16, 16, 8, wmma::precision::tf32, wmma::row_major> af[4];
            wmma::fragment<wmma::matrix_b, 16, 16, 8, wmma::precision::tf32, wmma::col_major> bf[2];
            #pragma unroll
            for (int f = 0; f < 4; f++)
                wmma::load_matrix_sync(af[f], &sA[c][(warp_m * 64 + f * 16) * GPAD + ks * 8], GPAD);
            #pragma unroll
            for (int g = 0; g < 2; g++)
                wmma::load_matrix_sync(bf[g], &sB[c][(warp_n * 32 + g * 16) * GPAD + ks * 8], GPAD);
            #pragma unroll
            for (int f = 0; f < 4; f++)
                #pragma unroll
                for (int g = 0; g < 2; g++)
                    wmma::mma_sync(acc[f][g], af[f], bf[g], acc[f][g]);
        }
        if (k < 31) {
            const int nb = c ^ 1;
            float* pa0 = &sA[nb][r0_ * GPAD + c0_]; float* pa1 = &sA[nb][r1_ * GPAD + c1_];
            float* pb0 = &sB[nb][r0_ * GPAD + c0_]; float* pb1 = &sB[nb][r1_ * GPAD + c1_];
            pa0[0]=wmma::__float_to_tf32(ra0.x); pa0[1]=wmma::__float_to_tf32(ra0.y);
            pa0[2]=wmma::__float_to_tf32(ra0.z); pa0[3]=wmma::__float_to_tf32(ra0.w);
            pa1[0]=wmma::__float_to_tf32(ra1.x); pa1[1]=wmma::__float_to_tf32(ra1.y);
            pa1[2]=wmma::__float_to_tf32(ra1.z); pa1[3]=wmma::__float_to_tf32(ra1.w);
            pb0[0]=wmma::__float_to_tf32(rb0.x); pb0[1]=wmma::__float_to_tf32(rb0.y);
            pb0[2]=wmma::__float_to_tf32(rb0.z); pb0[3]=wmma::__float_to_tf32(rb0.w);
            pb1[0]=wmma::__float_to_tf32(rb1.x); pb1[1]=wmma::__float_to_tf32(rb1.y);
            pb1[2]=wmma::__float_to_tf32(rb1.z); pb1[3]=wmma::__float_to_tf32(rb1.w);
        }
        __syncthreads();
    }

    // epilogue: stage each 16x16 frag through smem, add bias, vector store
    float* stage = &sA[0][wid * (16 * GPAD)];
    #pragma unroll
    for (int f = 0; f < 4; f++) {
        #pragma unroll
        for (int g = 0; g < 2; g++) {
            wmma::store_matrix_sync(stage, acc[f][g], GPAD, wmma::mem_row_major);
            __syncwarp();
            #pragma unroll
            for (int i = 0; i < 2; i++) {
                int v = lane * 2 + i;
                int r = v >> 2, cc = (v & 3) * 4;
                int orow = n0 + warp_m * 64 + f * 16 + r;
                int ocol = o0 + warp_n * 32 + g * 16 + cc;
                float4 s = *(const float4*)(stage + r * GPAD + cc);
                float4 bv = *(const float4*)(Bi + ocol);
                s.x += bv.x; s.y += bv.y; s.z += bv.z; s.w += bv.w;
                *(float4*)(Out + (size_t)orow * 512 + ocol) = s;
            }
            __syncwarp();
        }
    }
}

// =====================================================================
// Qrel (wmma tf32, unchanged from passing R3)
// =====================================================================
__global__ __launch_bounds__(256) void qrel_kernel(const float* __restrict__ vbias)
{
    __shared__ float sA[64 * GPAD];
    __shared__ float sB[64 * GPAD];

    const int b = blockIdx.z >> 3, h = blockIdx.z & 7;
    const int i0 = blockIdx.y * 64, m0 = blockIdx.x * 64;
    if (m0 + 63 < 321 - i0 || m0 > 767 - i0) return;   // band skip
    const float* Qb = g_Q + (size_t)b * LL * HIDD + h * 64;
    const float* Rb = g_R + h * 64;

    const int tid = threadIdx.x;
    const int wid = tid >> 5;
    const int warp_m = wid & 1;
    const int warp_n = wid >> 1;

    wmma::fragment<wmma::accumulator, 16, 16, 8, float> acc[2];
    wmma::fill_fragment(acc[0], 0.0f);
    wmma::fill_fragment(acc[1], 0.0f);

    for (int kc = 0; kc < 64; kc += 16) {
        {
            int v = tid;
            int row = v >> 2, col = (v & 3) * 4;
            float4 a  = *(const float4*)(Qb + (size_t)(i0 + row) * 512 + kc + col);
            float4 vb = *(const float4*)(vbias + h * 64 + kc + col);
            float4 w  = *(const float4*)(Rb + (size_t)(m0 + row) * 512 + kc + col);
            float* pa = sA + row * GPAD + col;
            float* pb = sB + row * GPAD + col;
            pa[0] = wmma::__float_to_tf32(a.x + vb.x);
            pa[1] = wmma::__float_to_tf32(a.y + vb.y);
            pa[2] = wmma::__float_to_tf32(a.z + vb.z);
            pa[3] = wmma::__float_to_tf32(a.w + vb.w);
            pb[0] = wmma::__float_to_tf32(w.x); pb[1] = wmma::__float_to_tf32(w.y);
            pb[2] = wmma::__float_to_tf32(w.z); pb[3] = wmma::__float_to_tf32(w.w);
        }
        __syncthreads();
        #pragma unroll
        for (int ks = 0; ks < 2; ks++) {
            wmma::fragment<wmma::matrix_a, 16, 16, 8, wmma::precision::tf32, wmma::row_major> af[2];
            wmma::fragment<wmma::matrix_b, 16, 16, 8, wmma::precision::tf32, wmma::col_major> bf;
            wmma::load_matrix_sync(af[0], sA + (warp_m * 32 +  0) * GPAD + ks * 8, GPAD);
            wmma::load_matrix_sync(af[1], sA + (warp_m * 32 + 16) * GPAD + ks * 8, GPAD);
            wmma::load_matrix_sync(bf,    sB + (warp_n * 16) * GPAD + ks * 8, GPAD);
            wmma::mma_sync(acc[0], af[0], bf, acc[0]);
            wmma::mma_sync(acc[1], af[1], bf, acc[1]);
        }
        __syncthreads();
    }

    float* dst = g_Qrel + ((size_t)(b * NHH + h) * LL + i0) * MM + m0;
    #pragma unroll
    for (int f = 0; f < 2; f++)
        wmma::store_matrix_sync(
            dst + (size_t)(warp_m * 32 + f * 16) * MM + warp_n * 16,
            acc[f], MM, wmma::mem_row_major);
}

// =====================================================================
// attention v2: flash-style online softmax, 52KB smem, 3-4 CTAs/SM
// per (i-tile 64, b, h): S tile in regs, running (m,l), P staged via smem
// =====================================================================
#define APAD 68
#define SMEM_ATTN (3 * 64 * APAD * 4)

__global__ __launch_bounds__(256) void attn_kernel(
    const float* __restrict__ ubias, const int* __restrict__ seq_len)
{
    extern __shared__ float sm[];
    float* sQuT = sm;                  // [d][i] stride APAD
    float* sKP  = sm + 64 * APAD;      // K^T [d][j], then P [i][j]
    float* sV   = sm + 2 * 64 * APAD;  // [j][d]

    const int i0 = blockIdx.x * 64;
    const int b  = blockIdx.y >> 3, h = blockIdx.y & 7;
    const int slen = seq_len[b];
    const int t = threadIdx.x;
    const int tx = t & 15, ty = t >> 4;
    const int lj = t >> 2, lk4 = (t & 3) * 4;

    // load Q tile + u_bias, transposed [d][i]
    #pragma unroll
    for (int r = 0; r < 4; r++) {
        int d0 = r * 16 + lk4;
        float4 q  = *(const float4*)(g_Q + ((size_t)(b * LL + i0 + lj)) * HIDD + h * 64 + d0);
        float4 u4 = *(const float4*)(ubias + h * 64 + d0);
        sQuT[(d0+0) * APAD + lj] = q.x + u4.x;
        sQuT[(d0+1) * APAD + lj] = q.y + u4.y;
        sQuT[(d0+2) * APAD + lj] = q.z + u4.z;
        sQuT[(d0+3) * APAD + lj] = q.w + u4.w;
    }

    const float* qr = g_Qrel + (size_t)(b * NHH + h) * LL * MM;

    float mrow[4] = {-3.4e38f, -3.4e38f, -3.4e38f, -3.4e38f};
    float lrow[4] = {0.f, 0.f, 0.f, 0.f};
    float accO[4][4] = {};

    for (int jt = 0; jt < 6; jt++) {
        const int j0 = jt * 64;
        if (jt > 0) __syncthreads();   // prev tile's PV reads of sKP/sV done
        // load K^T tile [d][j] and V tile [j][d]
        #pragma unroll
        for (int r = 0; r < 4; r++) {
            int d0 = r * 16 + lk4;
            float4 kv = *(const float4*)(g_K + ((size_t)(b * LL + j0 + lj)) * HIDD + h * 64 + d0);
            sKP[(d0+0) * APAD + lj] = kv.x;
            sKP[(d0+1) * APAD + lj] = kv.y;
            sKP[(d0+2) * APAD + lj] = kv.z;
            sKP[(d0+3) * APAD + lj] = kv.w;
            float4 vv = *(const float4*)(g_V + ((size_t)(b * LL + j0 + lj)) * HIDD + h * 64 + d0);
            *(float4*)&sV[lj * APAD + d0] = vv;
        }
        __syncthreads();

        // prefetch qrel for this thread's 4x4 patch
        float qv[4][4];
        #pragma unroll
        for (int ii = 0; ii < 4; ii++) {
            const int i = i0 + ty * 4 + ii;
            #pragma unroll
            for (int jj = 0; jj < 4; jj++) {
                const int j = j0 + tx * 4 + jj;
                qv[ii][jj] = __ldg(&qr[(size_t)i * MM + (j - i + 384)]);
            }
        }

        // S tile: acc = QuT . KT
        float acc[4][4] = {};
        #pragma unroll 16
        for (int d = 0; d < 64; d++) {
            float4 a4 = *(const float4*)&sQuT[d * APAD + ty * 4];
            float4 b4 = *(const float4*)&sKP[d * APAD + tx * 4];
            float ar[4] = {a4.x, a4.y, a4.z, a4.w};
            float br_[4] = {b4.x, b4.y, b4.z, b4.w};
            #pragma unroll
            for (int i = 0; i < 4; i++)
                #pragma unroll
                for (int j = 0; j < 4; j++)
                    acc[i][j] = fmaf(ar[i], br_[j], acc[i][j]);
        }

        // scores + online softmax update
        #pragma unroll
        for (int ii = 0; ii < 4; ii++) {
            float tmax = -3.4e38f;
            #pragma unroll
            for (int jj = 0; jj < 4; jj++) {
                const int j = j0 + tx * 4 + jj;
                float s = (acc[ii][jj] + qv[ii][jj]) * 0.125f;
                if (j >= slen) s = -1e15f;
                acc[ii][jj] = s;
                tmax = fmaxf(tmax, s);
            }
            #pragma unroll
            for (int off = 8; off; off >>= 1)
                tmax = fmaxf(tmax, __shfl_xor_sync(0xffffffffu, tmax, off));
            const float mn = fmaxf(mrow[ii], tmax);
            const float scale = __expf(mrow[ii] - mn);
            float ps = 0.f;
            #pragma unroll
            for (int jj = 0; jj < 4; jj++) {
                float e = __expf(acc[ii][jj] - mn);
                acc[ii][jj] = e;
                ps += e;
            }
            #pragma unroll
            for (int off = 8; off; off >>= 1)
                ps += __shfl_xor_sync(0xffffffffu, ps, off);
            lrow[ii] = lrow[ii] * scale + ps;
            mrow[ii] = mn;
            #pragma unroll
            for (int dd = 0; dd < 4; dd++)
                accO[ii][dd] *= scale;
        }

        __syncthreads();   // all reads of sKP (K^T) finished
        // write P into sKP as [i][j]
        #pragma unroll
        for (int ii = 0; ii < 4; ii++) {
            float4 p4;
            p4.x = acc[ii][0]; p4.y = acc[ii][1]; p4.z = acc[ii][2]; p4.w = acc[ii][3];
            *(float4*)&sKP[(ty * 4 + ii) * APAD + tx * 4] = p4;
        }
        __syncthreads();

        // accO += P . V
        #pragma unroll 8
        for (int j = 0; j < 64; j++) {
            float4 v4 = *(const float4*)&sV[j * APAD + tx * 4];
            float p0 = sKP[(ty * 4 + 0) * APAD + j];
            float p1 = sKP[(ty * 4 + 1) * APAD + j];
            float p2 = sKP[(ty * 4 + 2) * APAD + j];
            float p3 = sKP[(ty * 4 + 3) * APAD + j];
            accO[0][0] = fmaf(p0, v4.x, accO[0][0]); accO[0][1] = fmaf(p0, v4.y, accO[0][1]);
            accO[0][2] = fmaf(p0, v4.z, accO[0][2]); accO[0][3] = fmaf(p0, v4.w, accO[0][3]);
            accO[1][0] = fmaf(p1, v4.x, accO[1][0]); accO[1][1] = fmaf(p1, v4.y, accO[1][1]);
            accO[1][2] = fmaf(p1, v4.z, accO[1][2]); accO[1][3] = fmaf(p1, v4.w, accO[1][3]);
            accO[2][0] = fmaf(p2, v4.x, accO[2][0]); accO[2][1] = fmaf(p2, v4.y, accO[2][1]);
            accO[2][2] = fmaf(p2, v4.z, accO[2][2]); accO[2][3] = fmaf(p2, v4.w, accO[2][3]);
            accO[3][0] = fmaf(p3, v4.x, accO[3][0]); accO[3][1] = fmaf(p3, v4.y, accO[3][1]);
            accO[3][2] = fmaf(p3, v4.z, accO[3][2]); accO[3][3] = fmaf(p3, v4.w, accO[3][3]);
        }
    }

    #pragma unroll
    for (int ii = 0; ii < 4; ii++) {
        const float inv = 1.f / lrow[ii];
        float4 o;
        o.x = accO[ii][0] * inv; o.y = accO[ii][1] * inv;
        o.z = accO[ii][2] * inv; o.w = accO[ii][3] * inv;
        *(float4*)(g_O + ((size_t)(b * LL + i0 + ty * 4 + ii)) * HIDD + h * 64 + tx * 4) = o;
    }
}

// ---------------- launch ----------------
extern "C" void kernel_launch(void* const* d_in, const int* in_sizes, int n_in,
                              void* d_out, int out_size)
{
    const float* key    = (const float*)d_in[0];
    const float* query  = (const float*)d_in[1];
    const float* value  = (const float*)d_in[2];
    const int*   slen   = (const int*)  d_in[3];
    const float* pe     = (const float*)d_in[4];
    const float* Wk     = (const float*)d_in[5];
    const float* bk     = (const float*)d_in[6];
    const float* Wq     = (const float*)d_in[7];
    const float* bq     = (const float*)d_in[8];
    const float* Wv     = (const float*)d_in[9];
    const float* bv     = (const float*)d_in[10];
    const float* Wr     = (const float*)d_in[11];
    const float* br_    = (const float*)d_in[12];
    const float* u_bias = (const float*)d_in[13];
    const float* v_bias = (const float*)d_in[14];
    const float* Wf     = (const float*)d_in[15];
    const float* bf     = (const float*)d_in[16];

    float *pK, *pQ, *pV, *pR, *pO;
    cudaGetSymbolAddress((void**)&pK, g_K);
    cudaGetSymbolAddress((void**)&pQ, g_Q);
    cudaGetSymbolAddress((void**)&pV, g_V);
    cudaGetSymbolAddress((void**)&pR, g_R);
    cudaGetSymbolAddress((void**)&pO, g_O);

    cudaFuncSetAttribute(attn_kernel, cudaFuncAttributeMaxDynamicSharedMemorySize, SMEM_ATTN);

    dim3 blk(256);
    tgemm512<<<dim3(4, 24, 4), blk>>>(
        key, query, value, pe,
        Wk, Wq, Wv, Wr,
        bk, bq, bv, br_,
        pK, pQ, pV, pR);
    qrel_kernel<<<dim3(12, 6, 64), blk>>>(v_bias);
    attn_kernel<<<dim3(6, 64), blk, SMEM_ATTN>>>(u_bias, slen);
    tgemm512<<<dim3(4, 24, 1), blk>>>(
        pO, nullptr, nullptr, nullptr,
        Wf, nullptr, nullptr, nullptr,
        bf, nullptr, nullptr, nullptr,
        (float*)d_out, nullptr, nullptr, nullptr);
}

// round 14
// speedup vs baseline: 1.7355x; 1.0142x over previous
#include <cuda_runtime.h>
#include <mma.h>
#include <cstdint>

using namespace nvcuda;

#define BB   8
#define LL   384
#define HIDD 512
#define NHH  8
#define MM   768   // 2*MAX_SEQ_LEN rows of pe / R

// ---------------- scratch (device globals, no allocation) ----------------
__device__ float g_K[BB*LL*HIDD];
__device__ float g_Q[BB*LL*HIDD];
__device__ float g_V[BB*LL*HIDD];
__device__ float g_R[MM*HIDD];
__device__ float g_Qrel[(size_t)BB*NHH*LL*MM];
__device__ float g_O[BB*LL*HIDD];

// =====================================================================
// wmma tf32 GEMM (NT), double-buffered, 128(M)x64(N) tiles:
//   out[n][o] = X[n][:]·W[o][:] + b[o],  K=512 in 32 chunks of 16.
// 8 warps in 4(M)x2(N); warp tile 32x32 (2x2 frags). 3 CTAs/SM.
// =====================================================================
#define GPAD 20

__global__ __launch_bounds__(256) void tgemm512(
    const float* __restrict__ X0, const float* __restrict__ X1,
    const float* __restrict__ X2, const float* __restrict__ X3,
    const float* __restrict__ W0, const float* __restrict__ W1,
    const float* __restrict__ W2, const float* __restrict__ W3,
    const float* __restrict__ B0, const float* __restrict__ B1,
    const float* __restrict__ B2, const float* __restrict__ B3,
    float* __restrict__ O0, float* __restrict__ O1,
    float* __restrict__ O2, float* __restrict__ O3)
{
    __shared__ float sA[2][128 * GPAD];
    __shared__ float sB[2][64 * GPAD];

    const int z = blockIdx.z;
    if (z == 3 && blockIdx.y >= 6) return;   // pe/R source has only 768 rows
    const float* X  = z == 0 ? X0 : z == 1 ? X1 : z == 2 ? X2 : X3;
    const float* W  = z == 0 ? W0 : z == 1 ? W1 : z == 2 ? W2 : W3;
    const float* Bi = z == 0 ? B0 : z == 1 ? B1 : z == 2 ? B2 : B3;
    float*      Out = z == 0 ? O0 : z == 1 ? O1 : z == 2 ? O2 : O3;

    const int n0 = blockIdx.y * 128;
    const int o0 = blockIdx.x * 64;
    const int tid = threadIdx.x;
    const int wid = tid >> 5;
    const int lane = tid & 31;
    const int warp_m = wid & 3;    // 0..3, 32 rows each
    const int warp_n = wid >> 2;   // 0..1, 32 cols each

    // A: 512 float4 per 128x16 chunk -> 2/thread ; B: 256 float4 -> 1/thread
    const int ar0 = (tid * 2) >> 2,     ac0 = ((tid * 2) & 3) * 4;
    const int ar1 = (tid * 2 + 1) >> 2, ac1 = ((tid * 2 + 1) & 3) * 4;
    const int br0 = tid >> 2,           bc0 = (tid & 3) * 4;

    wmma::fragment<wmma::accumulator, 16, 16, 8, float> acc[2][2];
    #pragma unroll
    for (int i = 0; i < 2; i++)
        #pragma unroll
        for (int j = 0; j < 2; j++)
            wmma::fill_fragment(acc[i][j], 0.0f);

    float4 ra0, ra1, rb0;
    // preload chunk 0
    ra0 = *(const float4*)(X + (size_t)(n0 + ar0) * 512 + ac0);
    ra1 = *(const float4*)(X + (size_t)(n0 + ar1) * 512 + ac1);
    rb0 = *(const float4*)(W + (size_t)(o0 + br0) * 512 + bc0);
    {
        float* pa0 = &sA[0][ar0 * GPAD + ac0]; float* pa1 = &sA[0][ar1 * GPAD + ac1];
        float* pb0 = &sB[0][br0 * GPAD + bc0];
        pa0[0]=wmma::__float_to_tf32(ra0.x); pa0[1]=wmma::__float_to_tf32(ra0.y);
        pa0[2]=wmma::__float_to_tf32(ra0.z); pa0[3]=wmma::__float_to_tf32(ra0.w);
        pa1[0]=wmma::__float_to_tf32(ra1.x); pa1[1]=wmma::__float_to_tf32(ra1.y);
        pa1[2]=wmma::__float_to_tf32(ra1.z); pa1[3]=wmma::__float_to_tf32(ra1.w);
        pb0[0]=wmma::__float_to_tf32(rb0.x); pb0[1]=wmma::__float_to_tf32(rb0.y);
        pb0[2]=wmma::__float_to_tf32(rb0.z); pb0[3]=wmma::__float_to_tf32(rb0.w);
    }
    __syncthreads();

    for (int k = 0; k < 32; k++) {
        const int c = k & 1;
        if (k < 31) {
            const int kc = (k + 1) * 16;
            ra0 = *(const float4*)(X + (size_t)(n0 + ar0) * 512 + kc + ac0);
            ra1 = *(const float4*)(X + (size_t)(n0 + ar1) * 512 + kc + ac1);
            rb0 = *(const float4*)(W + (size_t)(o0 + br0) * 512 + kc + bc0);
        }
        #pragma unroll
        for (int ks = 0; ks < 2; ks++) {
            wmma::fragment<wmma::matrix_a, 16, 16, 8, wmma::precision::tf32, wmma::row_major> af[2];
            wmma::fragment<wmma::matrix_b, 16, 16, 8, wmma::precision::tf32, wmma::col_major> bf[2];
            #pragma unroll
            for (int f = 0; f < 2; f++)
                wmma::load_matrix_sync(af[f], &sA[c][(warp_m * 32 + f * 16) * GPAD + ks * 8], GPAD);
            #pragma unroll
            for (int g = 0; g < 2; g++)
                wmma::load_matrix_sync(bf[g], &sB[c][(warp_n * 32 + g * 16) * GPAD + ks * 8], GPAD);
            #pragma unroll
            for (int f = 0; f < 2; f++)
                #pragma unroll
                for (int g = 0; g < 2; g++)
                    wmma::mma_sync(acc[f][g], af[f], bf[g], acc[f][g]);
        }
        if (k < 31) {
            const int nb = c ^ 1;
            float* pa0 = &sA[nb][ar0 * GPAD + ac0]; float* pa1 = &sA[nb][ar1 * GPAD + ac1];
            float* pb0 = &sB[nb][br0 * GPAD + bc0];
            pa0[0]=wmma::__float_to_tf32(ra0.x); pa0[1]=wmma::__float_to_tf32(ra0.y);
            pa0[2]=wmma::__float_to_tf32(ra0.z); pa0[3]=wmma::__float_to_tf32(ra0.w);
            pa1[0]=wmma::__float_to_tf32(ra1.x); pa1[1]=wmma::__float_to_tf32(ra1.y);
            pa1[2]=wmma::__float_to_tf32(ra1.z); pa1[3]=wmma::__float_to_tf32(ra1.w);
            pb0[0]=wmma::__float_to_tf32(rb0.x); pb0[1]=wmma::__float_to_tf32(rb0.y);
            pb0[2]=wmma::__float_to_tf32(rb0.z); pb0[3]=wmma::__float_to_tf32(rb0.w);
        }
        __syncthreads();
    }

    // epilogue: stage each 16x16 frag through smem, add bias, vector store
    float* stage = &sA[0][wid * (16 * GPAD)];
    #pragma unroll
    for (int f = 0; f < 2; f++) {
        #pragma unroll
        for (int g = 0; g < 2; g++) {
            wmma::store_matrix_sync(stage, acc[f][g], GPAD, wmma::mem_row_major);
            __syncwarp();
            #pragma unroll
            for (int i = 0; i < 2; i++) {
                int v = lane * 2 + i;
                int r = v >> 2, cc = (v & 3) * 4;
                int orow = n0 + warp_m * 32 + f * 16 + r;
                int ocol = o0 + warp_n * 32 + g * 16 + cc;
                float4 s = *(const float4*)(stage + r * GPAD + cc);
                float4 bv = *(const float4*)(Bi + ocol);
                s.x += bv.x; s.y += bv.y; s.z += bv.z; s.w += bv.w;
                *(float4*)(Out + (size_t)orow * 512 + ocol) = s;
            }
            __syncwarp();
        }
    }
}

// =====================================================================
// Qrel (wmma tf32, unchanged from passing R13)
// =====================================================================
__global__ __launch_bounds__(256) void qrel_kernel(const float* __restrict__ vbias)
{
    __shared__ float sA[64 * GPAD];
    __shared__ float sB[64 * GPAD];

    const int b = blockIdx.z >> 3, h = blockIdx.z & 7;
    const int i0 = blockIdx.y * 64, m0 = blockIdx.x * 64;
    if (m0 + 63 < 321 - i0 || m0 > 767 - i0) return;   // band skip
    const float* Qb = g_Q + (size_t)b * LL * HIDD + h * 64;
    const float* Rb = g_R + h * 64;

    const int tid = threadIdx.x;
    const int wid = tid >> 5;
    const int warp_m = wid & 1;
    const int warp_n = wid >> 1;

    wmma::fragment<wmma::accumulator, 16, 16, 8, float> acc[2];
    wmma::fill_fragment(acc[0], 0.0f);
    wmma::fill_fragment(acc[1], 0.0f);

    for (int kc = 0; kc < 64; kc += 16) {
        {
            int v = tid;
            int row = v >> 2, col = (v & 3) * 4;
            float4 a  = *(const float4*)(Qb + (size_t)(i0 + row) * 512 + kc + col);
            float4 vb = *(const float4*)(vbias + h * 64 + kc + col);
            float4 w  = *(const float4*)(Rb + (size_t)(m0 + row) * 512 + kc + col);
            float* pa = sA + row * GPAD + col;
            float* pb = sB + row * GPAD + col;
            pa[0] = wmma::__float_to_tf32(a.x + vb.x);
            pa[1] = wmma::__float_to_tf32(a.y + vb.y);
            pa[2] = wmma::__float_to_tf32(a.z + vb.z);
            pa[3] = wmma::__float_to_tf32(a.w + vb.w);
            pb[0] = wmma::__float_to_tf32(w.x); pb[1] = wmma::__float_to_tf32(w.y);
            pb[2] = wmma::__float_to_tf32(w.z); pb[3] = wmma::__float_to_tf32(w.w);
        }
        __syncthreads();
        #pragma unroll
        for (int ks = 0; ks < 2; ks++) {
            wmma::fragment<wmma::matrix_a, 16, 16, 8, wmma::precision::tf32, wmma::row_major> af[2];
            wmma::fragment<wmma::matrix_b, 16, 16, 8, wmma::precision::tf32, wmma::col_major> bf;
            wmma::load_matrix_sync(af[0], sA + (warp_m * 32 +  0) * GPAD + ks * 8, GPAD);
            wmma::load_matrix_sync(af[1], sA + (warp_m * 32 + 16) * GPAD + ks * 8, GPAD);
            wmma::load_matrix_sync(bf,    sB + (warp_n * 16) * GPAD + ks * 8, GPAD);
            wmma::mma_sync(acc[0], af[0], bf, acc[0]);
            wmma::mma_sync(acc[1], af[1], bf, acc[1]);
        }
        __syncthreads();
    }

    float* dst = g_Qrel + ((size_t)(b * NHH + h) * LL + i0) * MM + m0;
    #pragma unroll
    for (int f = 0; f < 2; f++)
        wmma::store_matrix_sync(
            dst + (size_t)(warp_m * 32 + f * 16) * MM + warp_n * 16,
            acc[f], MM, wmma::mem_row_major);
}

// =====================================================================
// attention: flash-style online softmax (unchanged from passing R13)
// =====================================================================
#define APAD 68
#define SMEM_ATTN (3 * 64 * APAD * 4)

__global__ __launch_bounds__(256) void attn_kernel(
    const float* __restrict__ ubias, const int* __restrict__ seq_len)
{
    extern __shared__ float sm[];
    float* sQuT = sm;                  // [d][i] stride APAD
    float* sKP  = sm + 64 * APAD;      // K^T [d][j], then P [i][j]
    float* sV   = sm + 2 * 64 * APAD;  // [j][d]

    const int i0 = blockIdx.x * 64;
    const int b  = blockIdx.y >> 3, h = blockIdx.y & 7;
    const int slen = seq_len[b];
    const int t = threadIdx.x;
    const int tx = t & 15, ty = t >> 4;
    const int lj = t >> 2, lk4 = (t & 3) * 4;

    #pragma unroll
    for (int r = 0; r < 4; r++) {
        int d0 = r * 16 + lk4;
        float4 q  = *(const float4*)(g_Q + ((size_t)(b * LL + i0 + lj)) * HIDD + h * 64 + d0);
        float4 u4 = *(const float4*)(ubias + h * 64 + d0);
        sQuT[(d0+0) * APAD + lj] = q.x + u4.x;
        sQuT[(d0+1) * APAD + lj] = q.y + u4.y;
        sQuT[(d0+2) * APAD + lj] = q.z + u4.z;
        sQuT[(d0+3) * APAD + lj] = q.w + u4.w;
    }

    const float* qr = g_Qrel + (size_t)(b * NHH + h) * LL * MM;

    float mrow[4] = {-3.4e38f, -3.4e38f, -3.4e38f, -3.4e38f};
    float lrow[4] = {0.f, 0.f, 0.f, 0.f};
    float accO[4][4] = {};

    for (int jt = 0; jt < 6; jt++) {
        const int j0 = jt * 64;
        if (jt > 0) __syncthreads();
        #pragma unroll
        for (int r = 0; r < 4; r++) {
            int d0 = r * 16 + lk4;
            float4 kv = *(const float4*)(g_K + ((size_t)(b * LL + j0 + lj)) * HIDD + h * 64 + d0);
            sKP[(d0+0) * APAD + lj] = kv.x;
            sKP[(d0+1) * APAD + lj] = kv.y;
            sKP[(d0+2) * APAD + lj] = kv.z;
            sKP[(d0+3) * APAD + lj] = kv.w;
            float4 vv = *(const float4*)(g_V + ((size_t)(b * LL + j0 + lj)) * HIDD + h * 64 + d0);
            *(float4*)&sV[lj * APAD + d0] = vv;
        }
        __syncthreads();

        float qv[4][4];
        #pragma unroll
        for (int ii = 0; ii < 4; ii++) {
            const int i = i0 + ty * 4 + ii;
            #pragma unroll
            for (int jj = 0; jj < 4; jj++) {
                const int j = j0 + tx * 4 + jj;
                qv[ii][jj] = __ldg(&qr[(size_t)i * MM + (j - i + 384)]);
            }
        }

        float acc[4][4] = {};
        #pragma unroll 16
        for (int d = 0; d < 64; d++) {
            float4 a4 = *(const float4*)&sQuT[d * APAD + ty * 4];
            float4 b4 = *(const float4*)&sKP[d * APAD + tx * 4];
            float ar[4] = {a4.x, a4.y, a4.z, a4.w};
            float br_[4] = {b4.x, b4.y, b4.z, b4.w};
            #pragma unroll
            for (int i = 0; i < 4; i++)
                #pragma unroll
                for (int j = 0; j < 4; j++)
                    acc[i][j] = fmaf(ar[i], br_[j], acc[i][j]);
        }

        #pragma unroll
        for (int ii = 0; ii < 4; ii++) {
            float tmax = -3.4e38f;
            #pragma unroll
            for (int jj = 0; jj < 4; jj++) {
                const int j = j0 + tx * 4 + jj;
                float s = (acc[ii][jj] + qv[ii][jj]) * 0.125f;
                if (j >= slen) s = -1e15f;
                acc[ii][jj] = s;
                tmax = fmaxf(tmax, s);
            }
            #pragma unroll
            for (int off = 8; off; off >>= 1)
                tmax = fmaxf(tmax, __shfl_xor_sync(0xffffffffu, tmax, off));
            const float mn = fmaxf(mrow[ii], tmax);
            const float scale = __expf(mrow[ii] - mn);
            float ps = 0.f;
            #pragma unroll
            for (int jj = 0; jj < 4; jj++) {
                float e = __expf(acc[ii][jj] - mn);
                acc[ii][jj] = e;
                ps += e;
            }
            #pragma unroll
            for (int off = 8; off; off >>= 1)
                ps += __shfl_xor_sync(0xffffffffu, ps, off);
            lrow[ii] = lrow[ii] * scale + ps;
            mrow[ii] = mn;
            #pragma unroll
            for (int dd = 0; dd < 4; dd++)
                accO[ii][dd] *= scale;
        }

        __syncthreads();
        #pragma unroll
        for (int ii = 0; ii < 4; ii++) {
            float4 p4;
            p4.x = acc[ii][0]; p4.y = acc[ii][1]; p4.z = acc[ii][2]; p4.w = acc[ii][3];
            *(float4*)&sKP[(ty * 4 + ii) * APAD + tx * 4] = p4;
        }
        __syncthreads();

        #pragma unroll 8
        for (int j = 0; j < 64; j++) {
            float4 v4 = *(const float4*)&sV[j * APAD + tx * 4];
            float p0 = sKP[(ty * 4 + 0) * APAD + j];
            float p1 = sKP[(ty * 4 + 1) * APAD + j];
            float p2 = sKP[(ty * 4 + 2) * APAD + j];
            float p3 = sKP[(ty * 4 + 3) * APAD + j];
            accO[0][0] = fmaf(p0, v4.x, accO[0][0]); accO[0][1] = fmaf(p0, v4.y, accO[0][1]);
            accO[0][2] = fmaf(p0, v4.z, accO[0][2]); accO[0][3] = fmaf(p0, v4.w, accO[0][3]);
            accO[1][0] = fmaf(p1, v4.x, accO[1][0]); accO[1][1] = fmaf(p1, v4.y, accO[1][1]);
            accO[1][2] = fmaf(p1, v4.z, accO[1][2]); accO[1][3] = fmaf(p1, v4.w, accO[1][3]);
            accO[2][0] = fmaf(p2, v4.x, accO[2][0]); accO[2][1] = fmaf(p2, v4.y, accO[2][1]);
            accO[2][2] = fmaf(p2, v4.z, accO[2][2]); accO[2][3] = fmaf(p2, v4.w, accO[2][3]);
            accO[3][0] = fmaf(p3, v4.x, accO[3][0]); accO[3][1] = fmaf(p3, v4.y, accO[3][1]);
            accO[3][2] = fmaf(p3, v4.z, accO[3][2]); accO[3][3] = fmaf(p3, v4.w, accO[3][3]);
        }
    }

    #pragma unroll
    for (int ii = 0; ii < 4; ii++) {
        const float inv = 1.f / lrow[ii];
        float4 o;
        o.x = accO[ii][0] * inv; o.y = accO[ii][1] * inv;
        o.z = accO[ii][2] * inv; o.w = accO[ii][3] * inv;
        *(float4*)(g_O + ((size_t)(b * LL + i0 + ty * 4 + ii)) * HIDD + h * 64 + tx * 4) = o;
    }
}

// ---------------- launch ----------------
extern "C" void kernel_launch(void* const* d_in, const int* in_sizes, int n_in,
                              void* d_out, int out_size)
{
    const float* key    = (const float*)d_in[0];
    const float* query  = (const float*)d_in[1];
    const float* value  = (const float*)d_in[2];
    const int*   slen   = (const int*)  d_in[3];
    const float* pe     = (const float*)d_in[4];
    const float* Wk     = (const float*)d_in[5];
    const float* bk     = (const float*)d_in[6];
    const float* Wq     = (const float*)d_in[7];
    const float* bq     = (const float*)d_in[8];
    const float* Wv     = (const float*)d_in[9];
    const float* bv     = (const float*)d_in[10];
    const float* Wr     = (const float*)d_in[11];
    const float* br_    = (const float*)d_in[12];
    const float* u_bias = (const float*)d_in[13];
    const float* v_bias = (const float*)d_in[14];
    const float* Wf     = (const float*)d_in[15];
    const float* bf     = (const float*)d_in[16];

    float *pK, *pQ, *pV, *pR, *pO;
    cudaGetSymbolAddress((void**)&pK, g_K);
    cudaGetSymbolAddress((void**)&pQ, g_Q);
    cudaGetSymbolAddress((void**)&pV, g_V);
    cudaGetSymbolAddress((void**)&pR, g_R);
    cudaGetSymbolAddress((void**)&pO, g_O);

    cudaFuncSetAttribute(attn_kernel, cudaFuncAttributeMaxDynamicSharedMemorySize, SMEM_ATTN);

    dim3 blk(256);
    // merged K/Q/V/R projections: N tiles of 64 -> grid.x = 8
    tgemm512<<<dim3(8, 24, 4), blk>>>(
        key, query, value, pe,
        Wk, Wq, Wv, Wr,
        bk, bq, bv, br_,
        pK, pQ, pV, pR);
    qrel_kernel<<<dim3(12, 6, 64), blk>>>(v_bias);
    attn_kernel<<<dim3(6, 64), blk, SMEM_ATTN>>>(u_bias, slen);
    tgemm512<<<dim3(8, 24, 1), blk>>>(
        pO, nullptr, nullptr, nullptr,
        Wf, nullptr, nullptr, nullptr,
        bf, nullptr, nullptr, nullptr,
        (float*)d_out, nullptr, nullptr, nullptr);
}